// round 16
// baseline (speedup 1.0000x reference)
#include <cuda_runtime.h>
#include <cuda_fp16.h>
#include <math.h>
#include <stdint.h>

#define N_NODES 50000
#define N_EDGES 800000
#define N_GRAPHS 64
#define EPSLN 1e-5f
#define SCAN_NBLK 196  // ceil(50000/256)

// ---------------- static scratch (no allocation allowed) ----------------
__device__ __align__(128) float  g_bufC[(size_t)N_NODES * 256];   // fp32: fc pre-LN, then x3
__device__ __align__(128) __half g_xh[(size_t)N_NODES * 128];
__device__ __align__(128) __half g_aggh[(size_t)N_NODES * 256];   // spmm1 out (128) & spmm3 out (256)
__device__ __align__(128) __half g_bufBh[(size_t)N_NODES * 512];  // x1 || f1
__device__ __align__(128) __half g_bufAh[(size_t)N_NODES * 256];  // gemm2 out
__device__ __align__(128) __half g_x2h[(size_t)N_NODES * 256];    // spmm2 out
__device__ __half g_W1h[128 * 256];
__device__ __half g_Wfch[128 * 256];
__device__ __half g_W2h[512 * 256];
__device__ __half g_W3h[256 * 256];
__device__ __align__(128) int2 g_colval[N_EDGES];   // packed (src, val bits)
__device__ int   g_rowptr[N_NODES + 1];
__device__ int   g_rowcur[N_NODES];
__device__ int   g_cnt[2 * N_NODES];          // [0:N) in-deg, [N:2N) out-deg
__device__ float g_innorm[N_NODES];
__device__ float g_outnorm[N_NODES];
__device__ int   g_blocksum[256];

// ---------------- helpers ----------------
__device__ __forceinline__ void cp_async16(void* smem, const void* gmem) {
    unsigned saddr = (unsigned)__cvta_generic_to_shared(smem);
    asm volatile("cp.async.cg.shared.global [%0], [%1], 16;\n" :: "r"(saddr), "l"(gmem));
}
__device__ __forceinline__ void cp_async16_zfill(void* smem, const void* gmem, bool valid) {
    unsigned saddr = (unsigned)__cvta_generic_to_shared(smem);
    int sz = valid ? 16 : 0;
    asm volatile("cp.async.cg.shared.global [%0], [%1], 16, %2;\n" :: "r"(saddr), "l"(gmem), "r"(sz));
}
__device__ __forceinline__ void cp_async_commit() { asm volatile("cp.async.commit_group;\n"); }
__device__ __forceinline__ void cp_async_wait0() { asm volatile("cp.async.wait_group 0;\n"); }
__device__ __forceinline__ void cp_async_wait1() { asm volatile("cp.async.wait_group 1;\n"); }

__device__ __forceinline__ void ldsm_x4(unsigned& r0, unsigned& r1, unsigned& r2, unsigned& r3, unsigned addr) {
    asm volatile("ldmatrix.sync.aligned.m8n8.x4.shared.b16 {%0,%1,%2,%3}, [%4];"
                 : "=r"(r0), "=r"(r1), "=r"(r2), "=r"(r3) : "r"(addr));
}
__device__ __forceinline__ void ldsm_x4t(unsigned& r0, unsigned& r1, unsigned& r2, unsigned& r3, unsigned addr) {
    asm volatile("ldmatrix.sync.aligned.m8n8.x4.trans.shared.b16 {%0,%1,%2,%3}, [%4];"
                 : "=r"(r0), "=r"(r1), "=r"(r2), "=r"(r3) : "r"(addr));
}
__device__ __forceinline__ void mma16816(float& c0, float& c1, float& c2, float& c3,
                                         unsigned a0, unsigned a1, unsigned a2, unsigned a3,
                                         unsigned b0, unsigned b1) {
    asm volatile("mma.sync.aligned.m16n8k16.row.col.f32.f16.f16.f32 "
                 "{%0,%1,%2,%3}, {%4,%5,%6,%7}, {%8,%9}, {%0,%1,%2,%3};"
                 : "+f"(c0), "+f"(c1), "+f"(c2), "+f"(c3)
                 : "r"(a0), "r"(a1), "r"(a2), "r"(a3), "r"(b0), "r"(b1));
}

// ---------------- CSR build ----------------
__global__ void k_hist(const int* __restrict__ src, const int* __restrict__ dst) {
    int e = blockIdx.x * blockDim.x + threadIdx.x;
    if (e < N_EDGES) {
        atomicAdd(&g_cnt[N_NODES + src[e]], 1);
        atomicAdd(&g_cnt[dst[e]], 1);
    }
}

// block-sums of in-degree + norms, fused
__global__ void k_scan1norms() {
    __shared__ int sh[256];
    int i = blockIdx.x * 256 + threadIdx.x;
    int cin = (i < N_NODES) ? g_cnt[i] : 0;
    if (i < N_NODES) {
        g_innorm[i]  = rsqrtf(fmaxf((float)cin, 1.0f));
        g_outnorm[i] = rsqrtf(fmaxf((float)g_cnt[N_NODES + i], 1.0f));
    }
    sh[threadIdx.x] = cin;
    __syncthreads();
    #pragma unroll
    for (int off = 128; off > 0; off >>= 1) {
        if (threadIdx.x < off) sh[threadIdx.x] += sh[threadIdx.x + off];
        __syncthreads();
    }
    if (threadIdx.x == 0) g_blocksum[blockIdx.x] = sh[0];
    if (i == 0) g_rowptr[N_NODES] = N_EDGES;
}

// per-block: reduce blocksums[0:bid) -> offset, then local scan -> rowptr & rowcur
__global__ void k_scan3b() {
    __shared__ int bs[256];
    __shared__ int sh[256];
    int t = threadIdx.x;
    int bid = blockIdx.x;
    bs[t] = (t < SCAN_NBLK && t < bid) ? g_blocksum[t] : 0;
    __syncthreads();
    #pragma unroll
    for (int off = 128; off > 0; off >>= 1) {
        if (t < off) bs[t] += bs[t + off];
        __syncthreads();
    }
    int boff = bs[0];

    int i = bid * 256 + t;
    int v = (i < N_NODES) ? g_cnt[i] : 0;
    sh[t] = v;
    __syncthreads();
    #pragma unroll
    for (int off = 1; off < 256; off <<= 1) {
        int tv = (t >= off) ? sh[t - off] : 0;
        __syncthreads();
        sh[t] += tv;
        __syncthreads();
    }
    if (i < N_NODES) {
        int rp = sh[t] - v + boff;
        g_rowptr[i] = rp;
        g_rowcur[i] = rp;
    }
}

__global__ void k_scatter(const int* __restrict__ src, const int* __restrict__ dst,
                          const float* __restrict__ w) {
    int e = blockIdx.x * blockDim.x + threadIdx.x;
    if (e < N_EDGES) {
        int d = dst[e];
        int slot = atomicAdd(&g_rowcur[d], 1);
        int s = src[e];
        g_colval[slot] = make_int2(s, __float_as_int(w[e] * g_outnorm[s]));
    }
}

// ---------------- fused fp32 -> fp16 conversion (x + all weights) ----------------
#define NX2   (N_NODES * 64)          // x: 6.4M floats -> 3.2M half2
#define NW1_2 16384                   // 128*256 floats -> 16384 half2
#define NW2_2 65536                   // 512*256 floats -> 65536 half2
#define NW3_2 32768                   // 256*256 floats -> 32768 half2
#define NCVT  (NX2 + 2 * NW1_2 + NW2_2 + NW3_2)

__global__ void k_f2h_all(const float* __restrict__ x, const float* __restrict__ W1,
                          const float* __restrict__ Wfc, const float* __restrict__ W2,
                          const float* __restrict__ W3) {
    int i = blockIdx.x * blockDim.x + threadIdx.x;
    if (i >= NCVT) return;
    const float* in; __half* out; int j = i;
    if (j < NX2) { in = x; out = g_xh; }
    else if ((j -= NX2) < NW1_2) { in = W1; out = g_W1h; }
    else if ((j -= NW1_2) < NW1_2) { in = Wfc; out = g_Wfch; }
    else if ((j -= NW1_2) < NW2_2) { in = W2; out = g_W2h; }
    else { j -= NW2_2; in = W3; out = g_W3h; }
    float2 f = reinterpret_cast<const float2*>(in)[j];
    reinterpret_cast<__half2*>(out)[j] = __floats2half2_rn(f.x, f.y);
}

// ---------------- SpMM: warp per node, single accumulator, descriptor prefetch ----------------
template<int DIM, bool EPI>
__global__ void k_spmmh(const __half* __restrict__ x, __half* __restrict__ out) {
    int warp = threadIdx.x >> 5, lane = threadIdx.x & 31;
    int v = blockIdx.x * 8 + warp;
    if (v >= N_NODES) return;
    int e0 = g_rowptr[v], e1 = g_rowptr[v + 1];
    const int2* cv = g_colval;
    if (DIM == 128) {
        float a0 = 0.f, a1 = 0.f, a2 = 0.f, a3 = 0.f;
        const uint2* xv = reinterpret_cast<const uint2*>(x);
        if (e0 < e1) {
            int2 c = cv[e0];
            for (int e = e0; e < e1; ++e) {
                int2 cn = (e + 1 < e1) ? cv[e + 1] : c;   // prefetch next descriptor
                float w = __int_as_float(c.y);
                uint2 p = xv[(size_t)c.x * 32 + lane];
                float2 f0 = __half22float2(*reinterpret_cast<__half2*>(&p.x));
                float2 f1 = __half22float2(*reinterpret_cast<__half2*>(&p.y));
                a0 = fmaf(w, f0.x, a0); a1 = fmaf(w, f0.y, a1);
                a2 = fmaf(w, f1.x, a2); a3 = fmaf(w, f1.y, a3);
                c = cn;
            }
        }
        if (EPI) {
            float sc = g_innorm[v];
            a0 = fmaxf(a0 * sc, 0.f); a1 = fmaxf(a1 * sc, 0.f);
            a2 = fmaxf(a2 * sc, 0.f); a3 = fmaxf(a3 * sc, 0.f);
        }
        uint2 o;
        *reinterpret_cast<__half2*>(&o.x) = __floats2half2_rn(a0, a1);
        *reinterpret_cast<__half2*>(&o.y) = __floats2half2_rn(a2, a3);
        reinterpret_cast<uint2*>(out)[(size_t)v * 32 + lane] = o;
    } else {
        float a[8];
        #pragma unroll
        for (int i = 0; i < 8; i++) a[i] = 0.f;
        const uint4* xv = reinterpret_cast<const uint4*>(x);
        if (e0 < e1) {
            int2 c = cv[e0];
            for (int e = e0; e < e1; ++e) {
                int2 cn = (e + 1 < e1) ? cv[e + 1] : c;   // prefetch next descriptor
                float w = __int_as_float(c.y);
                uint4 p = xv[(size_t)c.x * 32 + lane];
                float2 f0 = __half22float2(*reinterpret_cast<__half2*>(&p.x));
                float2 f1 = __half22float2(*reinterpret_cast<__half2*>(&p.y));
                float2 f2 = __half22float2(*reinterpret_cast<__half2*>(&p.z));
                float2 f3 = __half22float2(*reinterpret_cast<__half2*>(&p.w));
                a[0] = fmaf(w, f0.x, a[0]); a[1] = fmaf(w, f0.y, a[1]);
                a[2] = fmaf(w, f1.x, a[2]); a[3] = fmaf(w, f1.y, a[3]);
                a[4] = fmaf(w, f2.x, a[4]); a[5] = fmaf(w, f2.y, a[5]);
                a[6] = fmaf(w, f3.x, a[6]); a[7] = fmaf(w, f3.y, a[7]);
                c = cn;
            }
        }
        if (EPI) {
            float sc = g_innorm[v];
            #pragma unroll
            for (int i = 0; i < 8; i++) a[i] = fmaxf(a[i] * sc, 0.f);
        }
        uint4 o;
        *reinterpret_cast<__half2*>(&o.x) = __floats2half2_rn(a[0], a[1]);
        *reinterpret_cast<__half2*>(&o.y) = __floats2half2_rn(a[2], a[3]);
        *reinterpret_cast<__half2*>(&o.z) = __floats2half2_rn(a[4], a[5]);
        *reinterpret_cast<__half2*>(&o.w) = __floats2half2_rn(a[6], a[7]);
        reinterpret_cast<uint4*>(out)[(size_t)v * 32 + lane] = o;
    }
}

// ---------------- fp16 tensor-core GEMM (3-stage cp.async pipeline) ----------------
#define A_STAGE_B (128 * 40 * 2)               // 10240
#define B_STAGE_B (32 * 136 * 2)               // 8704
#define B_REGION  (3 * A_STAGE_B)              // 30720
#define GEMM_SMEM (3 * (A_STAGE_B + B_STAGE_B))  // 56832

__device__ __forceinline__ void gemm16_body(
    const __half* __restrict__ A, const __half* __restrict__ B,
    void* __restrict__ Cout, int M, int K, int lda, int ldc, int epi, char* dsm) {

    int tid = threadIdx.x;
    int wid = tid >> 5, lane = tid & 31;
    int wm = wid >> 2, wn = wid & 3;          // warp grid 2 x 4
    int rowBase = blockIdx.x * 128;
    int colBase = blockIdx.y * 128;

    int arow0 = tid >> 2,          ac0 = (tid & 3) * 8;
    int arow1 = (tid + 256) >> 2,  ac1 = (tid & 3) * 8;
    int brow0 = tid >> 4,          bc  = (tid & 15) * 8;
    int brow1 = (tid + 256) >> 4;

    float acc[4][4][4];
    #pragma unroll
    for (int i = 0; i < 4; i++)
        #pragma unroll
        for (int j = 0; j < 4; j++)
            #pragma unroll
            for (int c = 0; c < 4; c++) acc[i][j][c] = 0.f;

    const int NT = K >> 5;

    auto issue = [&](int s, int kt) {
        __half* ab = (__half*)(dsm + s * A_STAGE_B);
        __half* bb = (__half*)(dsm + B_REGION + s * B_STAGE_B);
        bool v0 = (rowBase + arow0) < M, v1 = (rowBase + arow1) < M;
        const __half* p0 = A + (size_t)(v0 ? rowBase + arow0 : 0) * lda + kt + ac0;
        const __half* p1 = A + (size_t)(v1 ? rowBase + arow1 : 0) * lda + kt + ac1;
        cp_async16_zfill(ab + arow0 * 40 + ac0, p0, v0);
        cp_async16_zfill(ab + arow1 * 40 + ac1, p1, v1);
        cp_async16(bb + brow0 * 136 + bc, B + (size_t)(kt + brow0) * 256 + colBase + bc);
        cp_async16(bb + brow1 * 136 + bc, B + (size_t)(kt + brow1) * 256 + colBase + bc);
    };

    issue(0, 0); cp_async_commit();
    if (NT > 1) { issue(1, 32); cp_async_commit(); }

    unsigned sbase = (unsigned)__cvta_generic_to_shared(dsm);
    int l15 = lane & 15, l16sel = (lane & 16) ? 8 : 0;

    int s = 0;
    for (int it = 0; it < NT; ++it) {
        if (it + 1 < NT) cp_async_wait1(); else cp_async_wait0();
        __syncthreads();
        if (it + 2 < NT) {
            int s2 = s + 2; if (s2 >= 3) s2 -= 3;
            issue(s2, (it + 2) << 5);
            cp_async_commit();
        }

        unsigned abase = sbase + s * A_STAGE_B;
        unsigned bbase = sbase + B_REGION + s * B_STAGE_B;
        #pragma unroll
        for (int ks = 0; ks < 2; ++ks) {
            unsigned a[4][4];
            #pragma unroll
            for (int mt = 0; mt < 4; ++mt) {
                int row = wm * 64 + mt * 16 + l15;
                unsigned addr = abase + (row * 40 + ks * 16 + l16sel) * 2;
                ldsm_x4(a[mt][0], a[mt][1], a[mt][2], a[mt][3], addr);
            }
            unsigned b[2][4];
            #pragma unroll
            for (int np = 0; np < 2; ++np) {
                int krow = ks * 16 + l15;
                int col = wn * 32 + np * 16 + l16sel;
                unsigned addr = bbase + (krow * 136 + col) * 2;
                ldsm_x4t(b[np][0], b[np][1], b[np][2], b[np][3], addr);
            }
            #pragma unroll
            for (int mt = 0; mt < 4; ++mt)
                #pragma unroll
                for (int nt = 0; nt < 4; ++nt) {
                    unsigned b0 = (nt & 1) ? b[nt >> 1][2] : b[nt >> 1][0];
                    unsigned b1 = (nt & 1) ? b[nt >> 1][3] : b[nt >> 1][1];
                    mma16816(acc[mt][nt][0], acc[mt][nt][1], acc[mt][nt][2], acc[mt][nt][3],
                             a[mt][0], a[mt][1], a[mt][2], a[mt][3], b0, b1);
                }
        }
        if (++s >= 3) s -= 3;
    }

    int g = lane >> 2, t = lane & 3;
    #pragma unroll
    for (int mt = 0; mt < 4; ++mt) {
        int row_lo = rowBase + wm * 64 + mt * 16 + g;
        int row_hi = row_lo + 8;
        bool vlo = row_lo < M, vhi = row_hi < M;
        float slo = 1.f, shi = 1.f;
        if (epi == 1 || epi == 2) {
            if (vlo) slo = g_innorm[row_lo];
            if (vhi) shi = g_innorm[row_hi];
        }
        #pragma unroll
        for (int nt = 0; nt < 4; ++nt) {
            int col = colBase + wn * 32 + nt * 8 + 2 * t;
            float c0 = acc[mt][nt][0], c1 = acc[mt][nt][1];
            float c2 = acc[mt][nt][2], c3 = acc[mt][nt][3];
            if (epi == 1 || epi == 2) {
                c0 = fmaxf(c0 * slo, 0.f); c1 = fmaxf(c1 * slo, 0.f);
                c2 = fmaxf(c2 * shi, 0.f); c3 = fmaxf(c3 * shi, 0.f);
            }
            if (epi == 0 || epi == 1) {
                float* C = (float*)Cout;
                if (vlo) *reinterpret_cast<float2*>(C + (size_t)row_lo * ldc + col) = make_float2(c0, c1);
                if (vhi) *reinterpret_cast<float2*>(C + (size_t)row_hi * ldc + col) = make_float2(c2, c3);
            } else {
                __half* C = (__half*)Cout;
                if (vlo) *reinterpret_cast<__half2*>(C + (size_t)row_lo * ldc + col) = __floats2half2_rn(c0, c1);
                if (vhi) *reinterpret_cast<__half2*>(C + (size_t)row_hi * ldc + col) = __floats2half2_rn(c2, c3);
            }
        }
    }
}

template<int EPI>
__global__ void __launch_bounds__(256, 2)
k_gemm16(const __half* __restrict__ A, const __half* __restrict__ B,
         void* __restrict__ Cout, int M, int K, int lda, int ldc) {
    extern __shared__ __align__(16) char dsm[];
    gemm16_body(A, B, Cout, M, K, lda, ldc, EPI, dsm);
}

// conv1 GEMM (z=0: aggh@W1 -> half innorm+relu, ldc 512) merged with
// fc GEMM    (z=1: xh@Wfc -> fp32 plain, ldc 256). Both K=128.
__global__ void __launch_bounds__(256, 2)
k_gemm16_dual(const __half* __restrict__ A0, const __half* __restrict__ B0, void* __restrict__ C0,
              const __half* __restrict__ A1, const __half* __restrict__ B1, void* __restrict__ C1,
              int M) {
    extern __shared__ __align__(16) char dsm[];
    if (blockIdx.z == 0) gemm16_body(A0, B0, C0, M, 128, 128, 512, 2, dsm);
    else                 gemm16_body(A1, B1, C1, M, 128, 128, 256, 0, dsm);
}

// ---------------- LayerNorm + relu (fp32 in, half out) ----------------
__global__ void k_ln_relu(const float* __restrict__ in, const float* __restrict__ gamma,
                          const float* __restrict__ beta, __half* __restrict__ out) {
    __shared__ float ws[8], ws2[8];
    int row = blockIdx.x, c = threadIdx.x;
    float v = in[(size_t)row * 256 + c];
    float s = v, s2 = v * v;
    #pragma unroll
    for (int off = 16; off > 0; off >>= 1) {
        s  += __shfl_xor_sync(0xffffffffu, s, off);
        s2 += __shfl_xor_sync(0xffffffffu, s2, off);
    }
    int wid = c >> 5, lane = c & 31;
    if (lane == 0) { ws[wid] = s; ws2[wid] = s2; }
    __syncthreads();
    float tot = 0.f, tot2 = 0.f;
    #pragma unroll
    for (int i = 0; i < 8; i++) { tot += ws[i]; tot2 += ws2[i]; }
    float mu = tot * (1.0f / 256.0f);
    float var = tot2 * (1.0f / 256.0f) - mu * mu;
    float o = (v - mu) * rsqrtf(var + EPSLN) * gamma[c] + beta[c];
    out[(size_t)row * 512 + c] = __float2half_rn(fmaxf(o, 0.f));
}

// ---------------- readout: binary-search graph range, then sum ----------------
__global__ void k_readout(const int* __restrict__ gid, const float* __restrict__ x3,
                          float* __restrict__ out) {
    int g = blockIdx.x, c = threadIdx.x;
    int lo = 0, hi = N_NODES;
    while (lo < hi) { int mid = (lo + hi) >> 1; if (gid[mid] < g) lo = mid + 1; else hi = mid; }
    int s = lo;
    hi = N_NODES;
    while (lo < hi) { int mid = (lo + hi) >> 1; if (gid[mid] < g + 1) lo = mid + 1; else hi = mid; }
    int e = lo;

    float a0 = 0.f, a1 = 0.f, a2 = 0.f, a3 = 0.f;
    int r = s;
    for (; r + 4 <= e; r += 4) {
        a0 += x3[(size_t)(r + 0) * 256 + c];
        a1 += x3[(size_t)(r + 1) * 256 + c];
        a2 += x3[(size_t)(r + 2) * 256 + c];
        a3 += x3[(size_t)(r + 3) * 256 + c];
    }
    for (; r < e; ++r) a0 += x3[(size_t)r * 256 + c];
    out[(size_t)g * 256 + c] = (a0 + a1) + (a2 + a3);
}

// ---------------- launch ----------------
extern "C" void kernel_launch(void* const* d_in, const int* in_sizes, int n_in,
                              void* d_out, int out_size) {
    const float* x     = (const float*)d_in[0];
    const float* w     = (const float*)d_in[1];
    const float* W1    = (const float*)d_in[2];
    const float* Wfc   = (const float*)d_in[3];
    const float* gamma = (const float*)d_in[4];
    const float* beta  = (const float*)d_in[5];
    const float* W2    = (const float*)d_in[6];
    const float* W3    = (const float*)d_in[7];
    const int*   src   = (const int*)d_in[8];
    const int*   dst   = (const int*)d_in[9];
    const int*   gid   = (const int*)d_in[10];
    float* out = (float*)d_out;

    float *bufC;
    __half *xh, *aggh, *bufBh, *bufAh, *x2h, *W1h, *Wfch, *W2h, *W3h;
    int *cnt;
    cudaGetSymbolAddress((void**)&bufC, g_bufC);
    cudaGetSymbolAddress((void**)&xh, g_xh);
    cudaGetSymbolAddress((void**)&aggh, g_aggh);
    cudaGetSymbolAddress((void**)&bufBh, g_bufBh);
    cudaGetSymbolAddress((void**)&bufAh, g_bufAh);
    cudaGetSymbolAddress((void**)&x2h, g_x2h);
    cudaGetSymbolAddress((void**)&W1h, g_W1h);
    cudaGetSymbolAddress((void**)&Wfch, g_Wfch);
    cudaGetSymbolAddress((void**)&W2h, g_W2h);
    cudaGetSymbolAddress((void**)&W3h, g_W3h);
    cudaGetSymbolAddress((void**)&cnt, g_cnt);

    cudaFuncSetAttribute(k_gemm16<1>, cudaFuncAttributeMaxDynamicSharedMemorySize, GEMM_SMEM);
    cudaFuncSetAttribute(k_gemm16<3>, cudaFuncAttributeMaxDynamicSharedMemorySize, GEMM_SMEM);
    cudaFuncSetAttribute(k_gemm16_dual, cudaFuncAttributeMaxDynamicSharedMemorySize, GEMM_SMEM);

    const int TB = 256;
    int edgeBlocks = (N_EDGES + TB - 1) / TB;
    int spmmBlocks = (N_NODES + 7) / 8;
    dim3 gemmGrid((N_NODES + 127) / 128, 2);
    dim3 dualGrid((N_NODES + 127) / 128, 2, 2);

    // conversions (independent of graph preprocessing)
    k_f2h_all<<<(NCVT + TB - 1) / TB, TB>>>(x, W1, Wfc, W2, W3);

    // graph preprocessing
    cudaMemsetAsync(cnt, 0, 2 * N_NODES * sizeof(int));
    k_hist<<<edgeBlocks, TB>>>(src, dst);
    k_scan1norms<<<SCAN_NBLK, 256>>>();
    k_scan3b<<<SCAN_NBLK, 256>>>();
    k_scatter<<<edgeBlocks, TB>>>(src, dst, w);

    // conv1 agg, then merged [conv1 GEMM + fc GEMM]
    k_spmmh<128, false><<<spmmBlocks, TB>>>(xh, aggh);
    k_gemm16_dual<<<dualGrid, TB, GEMM_SMEM>>>(aggh, W1h, bufBh, xh, Wfch, bufC, N_NODES);
    k_ln_relu<<<N_NODES, TB>>>(bufC, gamma, beta, bufBh + 256);

    // conv2: (x1f1)@W2 -> agg -> *in_norm, relu -> x2 (half)
    k_gemm16<3><<<gemmGrid, TB, GEMM_SMEM>>>(bufBh, W2h, bufAh, N_NODES, 512, 512, 256);
    k_spmmh<256, true><<<spmmBlocks, TB>>>(bufAh, x2h);

    // conv3: agg(x2) -> @W3 -> *in_norm, relu -> x3 (fp32 bufC)
    k_spmmh<256, false><<<spmmBlocks, TB>>>(x2h, aggh);
    k_gemm16<1><<<gemmGrid, TB, GEMM_SMEM>>>(aggh, W3h, bufC, N_NODES, 256, 256, 256);

    // readout
    k_readout<<<N_GRAPHS, TB>>>(gid, bufC, out);
}

// round 17
// speedup vs baseline: 1.0889x; 1.0889x over previous
#include <cuda_runtime.h>
#include <cuda_fp16.h>
#include <math.h>
#include <stdint.h>

#define N_NODES 50000
#define N_EDGES 800000
#define N_GRAPHS 64
#define EPSLN 1e-5f
#define SCAN_NBLK 196  // ceil(50000/256)

// ---------------- static scratch (no allocation allowed) ----------------
__device__ __align__(128) float  g_bufC[(size_t)N_NODES * 256];   // fp32: fc pre-LN
__device__ __align__(128) __half g_xh[(size_t)N_NODES * 128];
__device__ __align__(128) __half g_aggh[(size_t)N_NODES * 256];   // spmm1 out (128) & spmm3 out (256)
__device__ __align__(128) __half g_bufBh[(size_t)N_NODES * 512];  // x1 || f1
__device__ __align__(128) __half g_bufAh[(size_t)N_NODES * 256];  // gemm2 out, then x3 (half)
__device__ __align__(128) __half g_x2h[(size_t)N_NODES * 256];    // spmm2 out
__device__ __half g_W1h[128 * 256];
__device__ __half g_Wfch[128 * 256];
__device__ __half g_W2h[512 * 256];
__device__ __half g_W3h[256 * 256];
__device__ __align__(128) float g_val[N_EDGES];
__device__ int   g_col[N_EDGES];
__device__ int   g_rowptr[N_NODES + 1];
__device__ int   g_rowcur[N_NODES];
__device__ int   g_cnt[2 * N_NODES];          // [0:N) in-deg, [N:2N) out-deg
__device__ float g_innorm[N_NODES];
__device__ float g_outnorm[N_NODES];
__device__ int   g_blocksum[256];

// ---------------- helpers ----------------
__device__ __forceinline__ void cp_async16(void* smem, const void* gmem) {
    unsigned saddr = (unsigned)__cvta_generic_to_shared(smem);
    asm volatile("cp.async.cg.shared.global [%0], [%1], 16;\n" :: "r"(saddr), "l"(gmem));
}
__device__ __forceinline__ void cp_async16_zfill(void* smem, const void* gmem, bool valid) {
    unsigned saddr = (unsigned)__cvta_generic_to_shared(smem);
    int sz = valid ? 16 : 0;
    asm volatile("cp.async.cg.shared.global [%0], [%1], 16, %2;\n" :: "r"(saddr), "l"(gmem), "r"(sz));
}
__device__ __forceinline__ void cp_async_commit() { asm volatile("cp.async.commit_group;\n"); }
__device__ __forceinline__ void cp_async_wait0() { asm volatile("cp.async.wait_group 0;\n"); }
__device__ __forceinline__ void cp_async_wait1() { asm volatile("cp.async.wait_group 1;\n"); }

__device__ __forceinline__ void ldsm_x4(unsigned& r0, unsigned& r1, unsigned& r2, unsigned& r3, unsigned addr) {
    asm volatile("ldmatrix.sync.aligned.m8n8.x4.shared.b16 {%0,%1,%2,%3}, [%4];"
                 : "=r"(r0), "=r"(r1), "=r"(r2), "=r"(r3) : "r"(addr));
}
__device__ __forceinline__ void ldsm_x4t(unsigned& r0, unsigned& r1, unsigned& r2, unsigned& r3, unsigned addr) {
    asm volatile("ldmatrix.sync.aligned.m8n8.x4.trans.shared.b16 {%0,%1,%2,%3}, [%4];"
                 : "=r"(r0), "=r"(r1), "=r"(r2), "=r"(r3) : "r"(addr));
}
__device__ __forceinline__ void mma16816(float& c0, float& c1, float& c2, float& c3,
                                         unsigned a0, unsigned a1, unsigned a2, unsigned a3,
                                         unsigned b0, unsigned b1) {
    asm volatile("mma.sync.aligned.m16n8k16.row.col.f32.f16.f16.f32 "
                 "{%0,%1,%2,%3}, {%4,%5,%6,%7}, {%8,%9}, {%0,%1,%2,%3};"
                 : "+f"(c0), "+f"(c1), "+f"(c2), "+f"(c3)
                 : "r"(a0), "r"(a1), "r"(a2), "r"(a3), "r"(b0), "r"(b1));
}

// ---------------- CSR build ----------------
__global__ void k_hist(const int* __restrict__ src, const int* __restrict__ dst) {
    int e = blockIdx.x * blockDim.x + threadIdx.x;
    if (e < N_EDGES) {
        atomicAdd(&g_cnt[N_NODES + src[e]], 1);
        atomicAdd(&g_cnt[dst[e]], 1);
    }
}

// block-sums of in-degree + norms, fused
__global__ void k_scan1norms() {
    __shared__ int sh[256];
    int i = blockIdx.x * 256 + threadIdx.x;
    int cin = (i < N_NODES) ? g_cnt[i] : 0;
    if (i < N_NODES) {
        g_innorm[i]  = rsqrtf(fmaxf((float)cin, 1.0f));
        g_outnorm[i] = rsqrtf(fmaxf((float)g_cnt[N_NODES + i], 1.0f));
    }
    sh[threadIdx.x] = cin;
    __syncthreads();
    #pragma unroll
    for (int off = 128; off > 0; off >>= 1) {
        if (threadIdx.x < off) sh[threadIdx.x] += sh[threadIdx.x + off];
        __syncthreads();
    }
    if (threadIdx.x == 0) g_blocksum[blockIdx.x] = sh[0];
    if (i == 0) g_rowptr[N_NODES] = N_EDGES;
}

// per-block: reduce blocksums[0:bid) -> offset, then local scan -> rowptr & rowcur
__global__ void k_scan3b() {
    __shared__ int bs[256];
    __shared__ int sh[256];
    int t = threadIdx.x;
    int bid = blockIdx.x;
    bs[t] = (t < SCAN_NBLK && t < bid) ? g_blocksum[t] : 0;
    __syncthreads();
    #pragma unroll
    for (int off = 128; off > 0; off >>= 1) {
        if (t < off) bs[t] += bs[t + off];
        __syncthreads();
    }
    int boff = bs[0];

    int i = bid * 256 + t;
    int v = (i < N_NODES) ? g_cnt[i] : 0;
    sh[t] = v;
    __syncthreads();
    #pragma unroll
    for (int off = 1; off < 256; off <<= 1) {
        int tv = (t >= off) ? sh[t - off] : 0;
        __syncthreads();
        sh[t] += tv;
        __syncthreads();
    }
    if (i < N_NODES) {
        int rp = sh[t] - v + boff;
        g_rowptr[i] = rp;
        g_rowcur[i] = rp;
    }
}

__global__ void k_scatter(const int* __restrict__ src, const int* __restrict__ dst,
                          const float* __restrict__ w) {
    int e = blockIdx.x * blockDim.x + threadIdx.x;
    if (e < N_EDGES) {
        int d = dst[e];
        int slot = atomicAdd(&g_rowcur[d], 1);
        int s = src[e];
        g_col[slot] = s;
        g_val[slot] = w[e] * g_outnorm[s];
    }
}

// ---------------- fused fp32 -> fp16 conversion (x + all weights) ----------------
#define NX2   (N_NODES * 64)          // x: 6.4M floats -> 3.2M half2
#define NW1_2 16384                   // 128*256 floats -> 16384 half2
#define NW2_2 65536                   // 512*256 floats -> 65536 half2
#define NW3_2 32768                   // 256*256 floats -> 32768 half2
#define NCVT  (NX2 + 2 * NW1_2 + NW2_2 + NW3_2)

__global__ void k_f2h_all(const float* __restrict__ x, const float* __restrict__ W1,
                          const float* __restrict__ Wfc, const float* __restrict__ W2,
                          const float* __restrict__ W3) {
    int i = blockIdx.x * blockDim.x + threadIdx.x;
    if (i >= NCVT) return;
    const float* in; __half* out; int j = i;
    if (j < NX2) { in = x; out = g_xh; }
    else if ((j -= NX2) < NW1_2) { in = W1; out = g_W1h; }
    else if ((j -= NW1_2) < NW1_2) { in = Wfc; out = g_Wfch; }
    else if ((j -= NW1_2) < NW2_2) { in = W2; out = g_W2h; }
    else { j -= NW2_2; in = W3; out = g_W3h; }
    float2 f = reinterpret_cast<const float2*>(in)[j];
    reinterpret_cast<__half2*>(out)[j] = __floats2half2_rn(f.x, f.y);
}

// ---------------- SpMM: warp per node (r13 proven shape) ----------------
template<int DIM, bool EPI>
__global__ void k_spmmh(const __half* __restrict__ x, __half* __restrict__ out) {
    int warp = threadIdx.x >> 5, lane = threadIdx.x & 31;
    int v = blockIdx.x * 8 + warp;
    if (v >= N_NODES) return;
    int e0 = g_rowptr[v], e1 = g_rowptr[v + 1];
    if (DIM == 128) {
        float a0 = 0.f, a1 = 0.f, a2 = 0.f, a3 = 0.f;
        const uint2* xv = reinterpret_cast<const uint2*>(x);
        for (int e = e0; e < e1; ++e) {
            int s = g_col[e];
            float w = g_val[e];
            uint2 p = xv[(size_t)s * 32 + lane];
            float2 f0 = __half22float2(*reinterpret_cast<__half2*>(&p.x));
            float2 f1 = __half22float2(*reinterpret_cast<__half2*>(&p.y));
            a0 = fmaf(w, f0.x, a0); a1 = fmaf(w, f0.y, a1);
            a2 = fmaf(w, f1.x, a2); a3 = fmaf(w, f1.y, a3);
        }
        if (EPI) {
            float sc = g_innorm[v];
            a0 = fmaxf(a0 * sc, 0.f); a1 = fmaxf(a1 * sc, 0.f);
            a2 = fmaxf(a2 * sc, 0.f); a3 = fmaxf(a3 * sc, 0.f);
        }
        uint2 o;
        *reinterpret_cast<__half2*>(&o.x) = __floats2half2_rn(a0, a1);
        *reinterpret_cast<__half2*>(&o.y) = __floats2half2_rn(a2, a3);
        reinterpret_cast<uint2*>(out)[(size_t)v * 32 + lane] = o;
    } else {
        float a[8];
        #pragma unroll
        for (int i = 0; i < 8; i++) a[i] = 0.f;
        const uint4* xv = reinterpret_cast<const uint4*>(x);
        for (int e = e0; e < e1; ++e) {
            int s = g_col[e];
            float w = g_val[e];
            uint4 p = xv[(size_t)s * 32 + lane];
            float2 f0 = __half22float2(*reinterpret_cast<__half2*>(&p.x));
            float2 f1 = __half22float2(*reinterpret_cast<__half2*>(&p.y));
            float2 f2 = __half22float2(*reinterpret_cast<__half2*>(&p.z));
            float2 f3 = __half22float2(*reinterpret_cast<__half2*>(&p.w));
            a[0] = fmaf(w, f0.x, a[0]); a[1] = fmaf(w, f0.y, a[1]);
            a[2] = fmaf(w, f1.x, a[2]); a[3] = fmaf(w, f1.y, a[3]);
            a[4] = fmaf(w, f2.x, a[4]); a[5] = fmaf(w, f2.y, a[5]);
            a[6] = fmaf(w, f3.x, a[6]); a[7] = fmaf(w, f3.y, a[7]);
        }
        if (EPI) {
            float sc = g_innorm[v];
            #pragma unroll
            for (int i = 0; i < 8; i++) a[i] = fmaxf(a[i] * sc, 0.f);
        }
        uint4 o;
        *reinterpret_cast<__half2*>(&o.x) = __floats2half2_rn(a[0], a[1]);
        *reinterpret_cast<__half2*>(&o.y) = __floats2half2_rn(a[2], a[3]);
        *reinterpret_cast<__half2*>(&o.z) = __floats2half2_rn(a[4], a[5]);
        *reinterpret_cast<__half2*>(&o.w) = __floats2half2_rn(a[6], a[7]);
        reinterpret_cast<uint4*>(out)[(size_t)v * 32 + lane] = o;
    }
}

// ---------------- fp16 tensor-core GEMM (3-stage cp.async pipeline) ----------------
#define A_STAGE_B (128 * 40 * 2)               // 10240
#define B_STAGE_B (32 * 136 * 2)               // 8704
#define B_REGION  (3 * A_STAGE_B)              // 30720
#define GEMM_SMEM (3 * (A_STAGE_B + B_STAGE_B))  // 56832

__device__ __forceinline__ void gemm16_body(
    const __half* __restrict__ A, const __half* __restrict__ B,
    void* __restrict__ Cout, int M, int K, int lda, int ldc, int epi, char* dsm) {

    int tid = threadIdx.x;
    int wid = tid >> 5, lane = tid & 31;
    int wm = wid >> 2, wn = wid & 3;          // warp grid 2 x 4
    int rowBase = blockIdx.x * 128;
    int colBase = blockIdx.y * 128;

    int arow0 = tid >> 2,          ac0 = (tid & 3) * 8;
    int arow1 = (tid + 256) >> 2,  ac1 = (tid & 3) * 8;
    int brow0 = tid >> 4,          bc  = (tid & 15) * 8;
    int brow1 = (tid + 256) >> 4;

    float acc[4][4][4];
    #pragma unroll
    for (int i = 0; i < 4; i++)
        #pragma unroll
        for (int j = 0; j < 4; j++)
            #pragma unroll
            for (int c = 0; c < 4; c++) acc[i][j][c] = 0.f;

    const int NT = K >> 5;

    auto issue = [&](int s, int kt) {
        __half* ab = (__half*)(dsm + s * A_STAGE_B);
        __half* bb = (__half*)(dsm + B_REGION + s * B_STAGE_B);
        bool v0 = (rowBase + arow0) < M, v1 = (rowBase + arow1) < M;
        const __half* p0 = A + (size_t)(v0 ? rowBase + arow0 : 0) * lda + kt + ac0;
        const __half* p1 = A + (size_t)(v1 ? rowBase + arow1 : 0) * lda + kt + ac1;
        cp_async16_zfill(ab + arow0 * 40 + ac0, p0, v0);
        cp_async16_zfill(ab + arow1 * 40 + ac1, p1, v1);
        cp_async16(bb + brow0 * 136 + bc, B + (size_t)(kt + brow0) * 256 + colBase + bc);
        cp_async16(bb + brow1 * 136 + bc, B + (size_t)(kt + brow1) * 256 + colBase + bc);
    };

    issue(0, 0); cp_async_commit();
    if (NT > 1) { issue(1, 32); cp_async_commit(); }

    unsigned sbase = (unsigned)__cvta_generic_to_shared(dsm);
    int l15 = lane & 15, l16sel = (lane & 16) ? 8 : 0;

    int s = 0;
    for (int it = 0; it < NT; ++it) {
        if (it + 1 < NT) cp_async_wait1(); else cp_async_wait0();
        __syncthreads();
        if (it + 2 < NT) {
            int s2 = s + 2; if (s2 >= 3) s2 -= 3;
            issue(s2, (it + 2) << 5);
            cp_async_commit();
        }

        unsigned abase = sbase + s * A_STAGE_B;
        unsigned bbase = sbase + B_REGION + s * B_STAGE_B;
        #pragma unroll
        for (int ks = 0; ks < 2; ++ks) {
            unsigned a[4][4];
            #pragma unroll
            for (int mt = 0; mt < 4; ++mt) {
                int row = wm * 64 + mt * 16 + l15;
                unsigned addr = abase + (row * 40 + ks * 16 + l16sel) * 2;
                ldsm_x4(a[mt][0], a[mt][1], a[mt][2], a[mt][3], addr);
            }
            unsigned b[2][4];
            #pragma unroll
            for (int np = 0; np < 2; ++np) {
                int krow = ks * 16 + l15;
                int col = wn * 32 + np * 16 + l16sel;
                unsigned addr = bbase + (krow * 136 + col) * 2;
                ldsm_x4t(b[np][0], b[np][1], b[np][2], b[np][3], addr);
            }
            #pragma unroll
            for (int mt = 0; mt < 4; ++mt)
                #pragma unroll
                for (int nt = 0; nt < 4; ++nt) {
                    unsigned b0 = (nt & 1) ? b[nt >> 1][2] : b[nt >> 1][0];
                    unsigned b1 = (nt & 1) ? b[nt >> 1][3] : b[nt >> 1][1];
                    mma16816(acc[mt][nt][0], acc[mt][nt][1], acc[mt][nt][2], acc[mt][nt][3],
                             a[mt][0], a[mt][1], a[mt][2], a[mt][3], b0, b1);
                }
        }
        if (++s >= 3) s -= 3;
    }

    int g = lane >> 2, t = lane & 3;
    #pragma unroll
    for (int mt = 0; mt < 4; ++mt) {
        int row_lo = rowBase + wm * 64 + mt * 16 + g;
        int row_hi = row_lo + 8;
        bool vlo = row_lo < M, vhi = row_hi < M;
        float slo = 1.f, shi = 1.f;
        if (epi == 1 || epi == 2) {
            if (vlo) slo = g_innorm[row_lo];
            if (vhi) shi = g_innorm[row_hi];
        }
        #pragma unroll
        for (int nt = 0; nt < 4; ++nt) {
            int col = colBase + wn * 32 + nt * 8 + 2 * t;
            float c0 = acc[mt][nt][0], c1 = acc[mt][nt][1];
            float c2 = acc[mt][nt][2], c3 = acc[mt][nt][3];
            if (epi == 1 || epi == 2) {
                c0 = fmaxf(c0 * slo, 0.f); c1 = fmaxf(c1 * slo, 0.f);
                c2 = fmaxf(c2 * shi, 0.f); c3 = fmaxf(c3 * shi, 0.f);
            }
            if (epi == 0 || epi == 1) {
                float* C = (float*)Cout;
                if (vlo) *reinterpret_cast<float2*>(C + (size_t)row_lo * ldc + col) = make_float2(c0, c1);
                if (vhi) *reinterpret_cast<float2*>(C + (size_t)row_hi * ldc + col) = make_float2(c2, c3);
            } else {
                __half* C = (__half*)Cout;
                if (vlo) *reinterpret_cast<__half2*>(C + (size_t)row_lo * ldc + col) = __floats2half2_rn(c0, c1);
                if (vhi) *reinterpret_cast<__half2*>(C + (size_t)row_hi * ldc + col) = __floats2half2_rn(c2, c3);
            }
        }
    }
}

template<int EPI>
__global__ void __launch_bounds__(256, 2)
k_gemm16(const __half* __restrict__ A, const __half* __restrict__ B,
         void* __restrict__ Cout, int M, int K, int lda, int ldc) {
    extern __shared__ __align__(16) char dsm[];
    gemm16_body(A, B, Cout, M, K, lda, ldc, EPI, dsm);
}

// conv1 GEMM (z=0: aggh@W1 -> half innorm+relu, ldc 512) merged with
// fc GEMM    (z=1: xh@Wfc -> fp32 plain, ldc 256). Both K=128.
__global__ void __launch_bounds__(256, 2)
k_gemm16_dual(const __half* __restrict__ A0, const __half* __restrict__ B0, void* __restrict__ C0,
              const __half* __restrict__ A1, const __half* __restrict__ B1, void* __restrict__ C1,
              int M) {
    extern __shared__ __align__(16) char dsm[];
    if (blockIdx.z == 0) gemm16_body(A0, B0, C0, M, 128, 128, 512, 2, dsm);
    else                 gemm16_body(A1, B1, C1, M, 128, 128, 256, 0, dsm);
}

// ---------------- LayerNorm + relu (fp32 in, half out) ----------------
__global__ void k_ln_relu(const float* __restrict__ in, const float* __restrict__ gamma,
                          const float* __restrict__ beta, __half* __restrict__ out) {
    __shared__ float ws[8], ws2[8];
    int row = blockIdx.x, c = threadIdx.x;
    float v = in[(size_t)row * 256 + c];
    float s = v, s2 = v * v;
    #pragma unroll
    for (int off = 16; off > 0; off >>= 1) {
        s  += __shfl_xor_sync(0xffffffffu, s, off);
        s2 += __shfl_xor_sync(0xffffffffu, s2, off);
    }
    int wid = c >> 5, lane = c & 31;
    if (lane == 0) { ws[wid] = s; ws2[wid] = s2; }
    __syncthreads();
    float tot = 0.f, tot2 = 0.f;
    #pragma unroll
    for (int i = 0; i < 8; i++) { tot += ws[i]; tot2 += ws2[i]; }
    float mu = tot * (1.0f / 256.0f);
    float var = tot2 * (1.0f / 256.0f) - mu * mu;
    float o = (v - mu) * rsqrtf(var + EPSLN) * gamma[c] + beta[c];
    out[(size_t)row * 512 + c] = __float2half_rn(fmaxf(o, 0.f));
}

// ---------------- readout: binary-search graph range, sum half x3 in fp32 ----------------
__global__ void k_readout(const int* __restrict__ gid, const __half* __restrict__ x3,
                          float* __restrict__ out) {
    int g = blockIdx.x, c = threadIdx.x;
    int lo = 0, hi = N_NODES;
    while (lo < hi) { int mid = (lo + hi) >> 1; if (gid[mid] < g) lo = mid + 1; else hi = mid; }
    int s = lo;
    hi = N_NODES;
    while (lo < hi) { int mid = (lo + hi) >> 1; if (gid[mid] < g + 1) lo = mid + 1; else hi = mid; }
    int e = lo;

    float a0 = 0.f, a1 = 0.f, a2 = 0.f, a3 = 0.f;
    int r = s;
    for (; r + 4 <= e; r += 4) {
        a0 += __half2float(x3[(size_t)(r + 0) * 256 + c]);
        a1 += __half2float(x3[(size_t)(r + 1) * 256 + c]);
        a2 += __half2float(x3[(size_t)(r + 2) * 256 + c]);
        a3 += __half2float(x3[(size_t)(r + 3) * 256 + c]);
    }
    for (; r < e; ++r) a0 += __half2float(x3[(size_t)r * 256 + c]);
    out[(size_t)g * 256 + c] = (a0 + a1) + (a2 + a3);
}

// ---------------- launch ----------------
extern "C" void kernel_launch(void* const* d_in, const int* in_sizes, int n_in,
                              void* d_out, int out_size) {
    const float* x     = (const float*)d_in[0];
    const float* w     = (const float*)d_in[1];
    const float* W1    = (const float*)d_in[2];
    const float* Wfc   = (const float*)d_in[3];
    const float* gamma = (const float*)d_in[4];
    const float* beta  = (const float*)d_in[5];
    const float* W2    = (const float*)d_in[6];
    const float* W3    = (const float*)d_in[7];
    const int*   src   = (const int*)d_in[8];
    const int*   dst   = (const int*)d_in[9];
    const int*   gid   = (const int*)d_in[10];
    float* out = (float*)d_out;

    float *bufC;
    __half *xh, *aggh, *bufBh, *bufAh, *x2h, *W1h, *Wfch, *W2h, *W3h;
    int *cnt;
    cudaGetSymbolAddress((void**)&bufC, g_bufC);
    cudaGetSymbolAddress((void**)&xh, g_xh);
    cudaGetSymbolAddress((void**)&aggh, g_aggh);
    cudaGetSymbolAddress((void**)&bufBh, g_bufBh);
    cudaGetSymbolAddress((void**)&bufAh, g_bufAh);
    cudaGetSymbolAddress((void**)&x2h, g_x2h);
    cudaGetSymbolAddress((void**)&W1h, g_W1h);
    cudaGetSymbolAddress((void**)&Wfch, g_Wfch);
    cudaGetSymbolAddress((void**)&W2h, g_W2h);
    cudaGetSymbolAddress((void**)&W3h, g_W3h);
    cudaGetSymbolAddress((void**)&cnt, g_cnt);

    cudaFuncSetAttribute(k_gemm16<2>, cudaFuncAttributeMaxDynamicSharedMemorySize, GEMM_SMEM);
    cudaFuncSetAttribute(k_gemm16<3>, cudaFuncAttributeMaxDynamicSharedMemorySize, GEMM_SMEM);
    cudaFuncSetAttribute(k_gemm16_dual, cudaFuncAttributeMaxDynamicSharedMemorySize, GEMM_SMEM);

    const int TB = 256;
    int edgeBlocks = (N_EDGES + TB - 1) / TB;
    int spmmBlocks = (N_NODES + 7) / 8;
    dim3 gemmGrid((N_NODES + 127) / 128, 2);
    dim3 dualGrid((N_NODES + 127) / 128, 2, 2);

    // conversions (independent of graph preprocessing)
    k_f2h_all<<<(NCVT + TB - 1) / TB, TB>>>(x, W1, Wfc, W2, W3);

    // graph preprocessing
    cudaMemsetAsync(cnt, 0, 2 * N_NODES * sizeof(int));
    k_hist<<<edgeBlocks, TB>>>(src, dst);
    k_scan1norms<<<SCAN_NBLK, 256>>>();
    k_scan3b<<<SCAN_NBLK, 256>>>();
    k_scatter<<<edgeBlocks, TB>>>(src, dst, w);

    // conv1 agg, then merged [conv1 GEMM + fc GEMM]
    k_spmmh<128, false><<<spmmBlocks, TB>>>(xh, aggh);
    k_gemm16_dual<<<dualGrid, TB, GEMM_SMEM>>>(aggh, W1h, bufBh, xh, Wfch, bufC, N_NODES);
    k_ln_relu<<<N_NODES, TB>>>(bufC, gamma, beta, bufBh + 256);

    // conv2: (x1f1)@W2 -> agg -> *in_norm, relu -> x2 (half)
    k_gemm16<3><<<gemmGrid, TB, GEMM_SMEM>>>(bufBh, W2h, bufAh, N_NODES, 512, 512, 256);
    k_spmmh<256, true><<<spmmBlocks, TB>>>(bufAh, x2h);

    // conv3: agg(x2) -> @W3 -> *in_norm, relu -> x3 (HALF, into bufAh — dead after spmm2)
    k_spmmh<256, false><<<spmmBlocks, TB>>>(x2h, aggh);
    k_gemm16<2><<<gemmGrid, TB, GEMM_SMEM>>>(aggh, W3h, bufAh, N_NODES, 256, 256, 256);

    // readout (half x3, fp32 accumulate)
    k_readout<<<N_GRAPHS, TB>>>(gid, bufAh, out);
}